// round 4
// baseline (speedup 1.0000x reference)
#include <cuda_runtime.h>
#include <cuda_bf16.h>
#include <cstdint>

#define B_ 8
#define D_ 256
#define T_ 4096
#define N_ 32768
#define K_ 8192

__device__ int    g_idx[N_];
__device__ float  g_z2[N_];
__device__ float  g_e2[K_];
__device__ float  g_lpart[N_];
__device__ uint4  g_zb4[N_ * 32];    // z bf16 token-major [N][256]
__device__ uint4  g_eb4[K_ * 32];    // emb bf16 [K][256]
__device__ float4 g_zt4[N_ * 64];    // z fp32 token-major [N][256]
__device__ float  g_bmin[256 * N_];  // [block][token] screen minima

// ---- PTX helpers (all legal on plain sm_100 target) ----
__device__ __forceinline__ uint32_t smem_u32(const void* p) {
    uint32_t a;
    asm("{ .reg .u64 t; cvta.to.shared.u64 t, %1; cvt.u32.u64 %0, t; }" : "=r"(a) : "l"(p));
    return a;
}
__device__ __forceinline__ void cp16(uint32_t dst, const void* src) {
    asm volatile("cp.async.cg.shared.global [%0], [%1], 16;" :: "r"(dst), "l"(src));
}
#define CP_COMMIT() asm volatile("cp.async.commit_group;" ::: "memory")
#define CP_WAIT0()  asm volatile("cp.async.wait_group 0;" ::: "memory")
__device__ __forceinline__ void ldmx4(uint32_t* r, uint32_t addr) {
    asm volatile("ldmatrix.sync.aligned.m8n8.x4.shared.b16 {%0,%1,%2,%3}, [%4];"
        : "=r"(r[0]), "=r"(r[1]), "=r"(r[2]), "=r"(r[3]) : "r"(addr));
}
__device__ __forceinline__ void mma16816(float* c, const uint32_t* a, const uint32_t* b) {
    asm volatile("mma.sync.aligned.m16n8k16.row.col.f32.bf16.bf16.f32 "
        "{%0,%1,%2,%3}, {%4,%5,%6,%7}, {%8,%9}, {%0,%1,%2,%3};"
        : "+f"(c[0]), "+f"(c[1]), "+f"(c[2]), "+f"(c[3])
        : "r"(a[0]), "r"(a[1]), "r"(a[2]), "r"(a[3]), "r"(b[0]), "r"(b[1]));
}

// ---- prep ----
__global__ void k_z2(const float* __restrict__ z) {
    int n = blockIdx.x * blockDim.x + threadIdx.x;
    int b = n >> 12, t = n & 4095;
    const float* p = z + (size_t)b * D_ * T_ + t;
    float s = 0.0f;
    #pragma unroll 8
    for (int d = 0; d < D_; d++) { float v = p[(size_t)d * T_]; s = __fadd_rn(s, __fmul_rn(v, v)); }
    g_z2[n] = s;
}
__global__ void k_e2(const float* __restrict__ emb) {
    int k = blockIdx.x * blockDim.x + threadIdx.x;
    const float* p = emb + (size_t)k * D_;
    float s = 0.0f;
    #pragma unroll 8
    for (int d = 0; d < D_; d++) { float v = __ldg(p + d); s = __fadd_rn(s, __fmul_rn(v, v)); }
    g_e2[k] = s;
}
__global__ void k_cvt(const float* __restrict__ emb) {
    int i = blockIdx.x * blockDim.x + threadIdx.x;
    ((__nv_bfloat16*)g_eb4)[i] = __float2bfloat16_rn(__ldg(emb + i));
}
__global__ void k_tr(const float* __restrict__ z) {
    __shared__ float ts[32][33];
    int t0 = blockIdx.x * 32, d0 = blockIdx.y * 32, b = blockIdx.z;
    int tx = threadIdx.x & 31, ty = threadIdx.x >> 5;
    #pragma unroll
    for (int p = 0; p < 4; p++) {
        int dd = ty + p * 8;
        ts[dd][tx] = z[((size_t)b * D_ + d0 + dd) * T_ + t0 + tx];
    }
    __syncthreads();
    float* zt = (float*)g_zt4;
    __nv_bfloat16* zb = (__nv_bfloat16*)g_zb4;
    #pragma unroll
    for (int p = 0; p < 4; p++) {
        int tt = ty + p * 8;
        float v = ts[tx][tt];
        size_t n = (size_t)b * T_ + t0 + tt;
        zt[n * D_ + d0 + tx] = v;
        zb[n * D_ + d0 + tx] = __float2bfloat16_rn(v);
    }
}

// ---- screen: mma.sync bf16 GEMM + block-min epilogue ----
#define A_STRIDE  264                      // bf16 row stride (conflict-free ldmatrix)
#define B_STRIDE  40
#define A_BYTES   (128 * A_STRIDE * 2)     // 67584
#define SM_B_OFF  A_BYTES
#define B_BUF     (128 * B_STRIDE * 2)     // 10240
#define SM_E2_OFF (SM_B_OFF + 2 * B_BUF)   // 88064
#define SMEM_SZ   (SM_E2_OFF + 512)        // 88576

__global__ __launch_bounds__(256, 2) void k_screen() {
    extern __shared__ __align__(16) char smem[];
    uint32_t sb = smem_u32(smem);
    int tid = threadIdx.x, lane = tid & 31, wid = tid >> 5;
    int wm = wid & 3, wn = wid >> 2;
    int n0 = blockIdx.x * 128;
    float* es2 = (float*)(smem + SM_E2_OFF);

    // A (128 tokens x 256 bf16) resident; B chunk 0
    const char* zsrc = (const char*)(g_zb4 + (size_t)n0 * 32);
    for (int i = tid; i < 128 * 32; i += 256) {
        int r = i >> 5, sg = i & 31;
        cp16(sb + r * (A_STRIDE * 2) + sg * 16, zsrc + r * 512 + sg * 16);
    }
    {
        const char* esrc = (const char*)g_eb4;
        for (int i = tid; i < 128 * 4; i += 256) {
            int r = i >> 2, sg = i & 3;
            cp16(sb + SM_B_OFF + r * (B_STRIDE * 2) + sg * 16, esrc + r * 512 + sg * 16);
        }
    }
    CP_COMMIT();
    CP_WAIT0();
    __syncthreads();

    float acc[2][8][4];
    for (int g = 0; g < 512; g++) {              // 64 tiles x 8 d-chunks
        int kt = g >> 3, c = g & 7;
        if (c == 0) {
            if (tid < 128) es2[tid] = g_e2[kt * 128 + tid];
            #pragma unroll
            for (int mb = 0; mb < 2; mb++)
                #pragma unroll
                for (int nb = 0; nb < 8; nb++)
                    #pragma unroll
                    for (int e = 0; e < 4; e++) acc[mb][nb][e] = 0.0f;
        }
        if (g + 1 < 512) {                       // prefetch next chunk
            int g2 = g + 1;
            uint32_t bdst = sb + SM_B_OFF + (g2 & 1) * B_BUF;
            const char* src = (const char*)g_eb4 + (size_t)(g2 >> 3) * 128 * 512 + (g2 & 7) * 64;
            for (int i = tid; i < 128 * 4; i += 256) {
                int r = i >> 2, sg = i & 3;
                cp16(bdst + r * (B_STRIDE * 2) + sg * 16, src + r * 512 + sg * 16);
            }
        }
        CP_COMMIT();

        uint32_t bBase = sb + SM_B_OFF + (g & 1) * B_BUF;
        #pragma unroll
        for (int s = 0; s < 2; s++) {            // two k16 steps per 32-d chunk
            uint32_t a[2][4];
            #pragma unroll
            for (int mb = 0; mb < 2; mb++)
                ldmx4(a[mb], sb + (uint32_t)(wm * 32 + mb * 16 + (lane & 15)) * (A_STRIDE * 2)
                           + (uint32_t)(c * 32 + s * 16 + (lane >> 4) * 8) * 2);
            #pragma unroll
            for (int pr = 0; pr < 4; pr++) {     // pairs of n8 blocks
                uint32_t b[4];
                ldmx4(b, bBase + (uint32_t)(wn * 64 + pr * 16 + (lane >> 4) * 8 + (lane & 7)) * (B_STRIDE * 2)
                            + (uint32_t)(s * 16 + ((lane >> 3) & 1) * 8) * 2);
                #pragma unroll
                for (int mb = 0; mb < 2; mb++) {
                    mma16816(acc[mb][pr * 2],     a[mb], b);
                    mma16816(acc[mb][pr * 2 + 1], a[mb], b + 2);
                }
            }
        }

        if (c == 7) {                            // epilogue: 32-code block minima
            #pragma unroll
            for (int j2 = 0; j2 < 2; j2++) {
                #pragma unroll
                for (int mb = 0; mb < 2; mb++) {
                    float m0 = 3.4e38f, m1 = 3.4e38f;
                    #pragma unroll
                    for (int nb = j2 * 4; nb < j2 * 4 + 4; nb++) {
                        int colb = wn * 64 + nb * 8 + (lane & 3) * 2;
                        float e2a = es2[colb], e2b = es2[colb + 1];
                        m0 = fminf(m0, fminf(fmaf(acc[mb][nb][0], -2.0f, e2a),
                                             fmaf(acc[mb][nb][1], -2.0f, e2b)));
                        m1 = fminf(m1, fminf(fmaf(acc[mb][nb][2], -2.0f, e2a),
                                             fmaf(acc[mb][nb][3], -2.0f, e2b)));
                    }
                    m0 = fminf(m0, __shfl_xor_sync(~0u, m0, 1));
                    m0 = fminf(m0, __shfl_xor_sync(~0u, m0, 2));
                    m1 = fminf(m1, __shfl_xor_sync(~0u, m1, 1));
                    m1 = fminf(m1, __shfl_xor_sync(~0u, m1, 2));
                    if ((lane & 3) == 0) {
                        int blk = kt * 4 + wn * 2 + j2;
                        int row = n0 + wm * 32 + mb * 16 + (lane >> 2);
                        g_bmin[(size_t)blk * N_ + row]     = m0;
                        g_bmin[(size_t)blk * N_ + row + 8] = m1;
                    }
                }
            }
        }
        CP_WAIT0();
        __syncthreads();
    }
}

// ---- rescue: exact rescore (numerics identical to round-1 passing kernel) ----
__global__ __launch_bounds__(128) void k_rescue(const float* __restrict__ emb) {
    __shared__ float zr[4][D_];
    int wid = threadIdx.x >> 5, lane = threadIdx.x & 31;
    int n = blockIdx.x * 4 + wid;

    const float4* zrow = (const float4*)(g_zt4 + (size_t)n * 64);
    #pragma unroll
    for (int q = 0; q < 2; q++) ((float4*)zr[wid])[lane + q * 32] = zrow[lane + q * 32];

    float bmv[8], mn = 3.4e38f;
    #pragma unroll
    for (int q = 0; q < 8; q++) {
        bmv[q] = g_bmin[(size_t)(q * 32 + lane) * N_ + n];
        mn = fminf(mn, bmv[q]);
    }
    #pragma unroll
    for (int o = 16; o > 0; o >>= 1) mn = fminf(mn, __shfl_xor_sync(0xffffffffu, mn, o));
    float thr = mn + 2.0e-3f;
    float z2 = g_z2[n];
    __syncwarp();

    float bd = 3.4e38f;
    int   bk = 0x7fffffff;
    for (int g = 0; g < 8; g++) {
        unsigned mask = __ballot_sync(0xffffffffu, bmv[g] <= thr);
        while (mask) {
            int bit = __ffs(mask) - 1;
            mask &= mask - 1;
            int k = (g * 32 + bit) * 32 + lane;
            const float4* e4 = (const float4*)(emb + (size_t)k * D_);
            const float4* z4 = (const float4*)zr[wid];
            float acc = 0.0f;
            #pragma unroll 16
            for (int f = 0; f < 64; f++) {
                float4 ev = __ldg(e4 + f);
                float4 zv = z4[f];
                acc = fmaf(zv.x, ev.x, acc); acc = fmaf(zv.y, ev.y, acc);
                acc = fmaf(zv.z, ev.z, acc); acc = fmaf(zv.w, ev.w, acc);
            }
            float dv = __fsub_rn(__fadd_rn(z2, g_e2[k]), __fmul_rn(2.0f, acc));
            if (dv < bd || (dv == bd && k < bk)) { bd = dv; bk = k; }
        }
    }
    #pragma unroll
    for (int o = 16; o > 0; o >>= 1) {
        float od = __shfl_xor_sync(0xffffffffu, bd, o);
        int   ok = __shfl_xor_sync(0xffffffffu, bk, o);
        if (od < bd || (od == bd && ok < bk)) { bd = od; bk = ok; }
    }
    if (lane == 0) g_idx[n] = bk;
}

// ---- output: coalesced gather + smem transpose + straight-through rounding ----
__global__ __launch_bounds__(256) void k_out(const float* __restrict__ emb,
                                             float* __restrict__ out,
                                             int write_zq, int write_idx, int idx_off) {
    __shared__ float s_sm[32][257];
    int tid = threadIdx.x, lane = tid & 31, w = tid >> 5;
    int n0 = blockIdx.x * 32;
    int b = n0 >> 12, t0 = n0 & 4095;
    const float* zt = (const float*)g_zt4;

    #pragma unroll
    for (int tt = 0; tt < 4; tt++) {
        int j = w * 4 + tt;
        int n = n0 + j;
        int idx = g_idx[n];
        const float* e  = emb + (size_t)idx * D_;
        const float* zp = zt + (size_t)n * D_;
        float lp = 0.0f;
        #pragma unroll
        for (int q = 0; q < 8; q++) {
            int d = lane + q * 32;
            float ev = __ldg(e + d);
            float zv = zp[d];
            float df = __fsub_rn(ev, zv);
            lp = fmaf(df, df, lp);
            if (write_zq) s_sm[j][d] = __fadd_rn(zv, df);
        }
        #pragma unroll
        for (int o = 16; o > 0; o >>= 1) lp += __shfl_xor_sync(~0u, lp, o);
        if (lane == 0) g_lpart[n] = lp;
    }
    if (write_idx && tid < 32) out[(size_t)idx_off + n0 + tid] = (float)g_idx[n0 + tid];
    if (!write_zq) return;
    __syncthreads();
    #pragma unroll
    for (int dc = 0; dc < 32; dc++) {
        int d = w + dc * 8;
        out[((size_t)b * D_ + d) * T_ + t0 + lane] = s_sm[lane][d];
    }
}
__global__ void k_loss(float* __restrict__ out, int loss_off) {
    __shared__ float sm[1024];
    int tid = threadIdx.x;
    float s = 0.0f;
    #pragma unroll 4
    for (int i = 0; i < 32; i++) s += g_lpart[tid * 32 + i];
    sm[tid] = s;
    __syncthreads();
    for (int w = 512; w > 0; w >>= 1) {
        if (tid < w) sm[tid] += sm[tid + w];
        __syncthreads();
    }
    if (tid == 0) out[loss_off] = 1.25f * (sm[0] / 8388608.0f);
}

extern "C" void kernel_launch(void* const* d_in, const int* in_sizes, int n_in,
                              void* d_out, int out_size) {
    const float* z   = (const float*)d_in[0];
    const float* emb = (const float*)d_in[1];
    if (n_in >= 2 && in_sizes[0] == K_ * D_ && in_sizes[1] == N_ * D_) {
        z = (const float*)d_in[1]; emb = (const float*)d_in[0];
    }
    float* out = (float*)d_out;

    cudaFuncSetAttribute(k_screen, cudaFuncAttributeMaxDynamicSharedMemorySize, SMEM_SZ);

    k_z2<<<N_ / 256, 256>>>(z);
    k_e2<<<K_ / 256, 256>>>(emb);
    k_cvt<<<K_ * D_ / 256, 256>>>(emb);
    k_tr<<<dim3(T_ / 32, D_ / 32, B_), 256>>>(z);
    k_screen<<<N_ / 128, 256, SMEM_SZ>>>();
    k_rescue<<<N_ / 4, 128>>>(emb);

    const int ZQ = N_ * D_;
    if (out_size == N_) {
        k_out<<<N_ / 32, 256>>>(emb, out, 0, 1, 0);
    } else {
        int write_zq = (out_size >= ZQ) ? 1 : 0;
        int write_loss = 0, write_idx = 0, idx_off = ZQ;
        if (out_size >= ZQ + 1 + N_) { write_loss = 1; write_idx = 1; idx_off = ZQ + 1; }
        else if (out_size == ZQ + N_) { write_idx = 1; idx_off = ZQ; }
        else if (out_size >= ZQ + 1) { write_loss = 1; }
        k_out<<<N_ / 32, 256>>>(emb, out, write_zq, write_idx, idx_off);
        if (write_loss) k_loss<<<1, 1024>>>(out, ZQ);
    }
}

// round 5
// speedup vs baseline: 2.5461x; 2.5461x over previous
#include <cuda_runtime.h>
#include <cstdint>

#define B_ 8
#define D_ 256
#define T_ 4096
#define N_ 32768
#define K_ 8192

// ---- device scratch (static; zero-initialized at load) ----
__device__ int      g_idx[N_];
__device__ float    g_z2[N_];
__device__ float    g_e2[K_];
__device__ float    g_lpart[N_];
__device__ float4   g_zt4[N_ * 64];   // z fp32 token-major [N][256]
__device__ int      g_zq8[N_ * 64];   // z int8 packed [N][64 ints]
__device__ int      g_eq8[K_ * 64];   // e int8 packed [K][64 ints]
__device__ float    g_zrs[N_];        // zstep_n * estep
__device__ float    g_thr[N_];        // per-token sound rescue margin
__device__ float    g_bmin[256 * N_]; // [block][token] screen minima
__device__ unsigned g_emax_bits;      // atomicMax accumulators (idempotent across replays)
__device__ unsigned g_sae_bits;

// ---------------------------------------------------------------------------
// prep: exact z2/e2 (identical numerics to reference rounding model)
// ---------------------------------------------------------------------------
__global__ void k_z2(const float* __restrict__ z) {
    int n = blockIdx.x * blockDim.x + threadIdx.x;
    int b = n >> 12, t = n & 4095;
    const float* p = z + (size_t)b * D_ * T_ + t;
    float s = 0.0f;
    #pragma unroll 8
    for (int d = 0; d < D_; d++) { float v = p[(size_t)d * T_]; s = __fadd_rn(s, __fmul_rn(v, v)); }
    g_z2[n] = s;
}
__global__ void k_e2(const float* __restrict__ emb) {
    int k = blockIdx.x * blockDim.x + threadIdx.x;
    const float* p = emb + (size_t)k * D_;
    float s = 0.0f;
    #pragma unroll 8
    for (int d = 0; d < D_; d++) { float v = __ldg(p + d); s = __fadd_rn(s, __fmul_rn(v, v)); }
    g_e2[k] = s;
}
// global max|e| (order-independent atomicMax on bits -> deterministic)
__global__ void k_emax(const float* __restrict__ emb) {
    int i0 = (blockIdx.x * blockDim.x + threadIdx.x) * 4;
    float m = 0.0f;
    #pragma unroll
    for (int c = 0; c < 4; c++) m = fmaxf(m, fabsf(__ldg(emb + i0 + c)));
    #pragma unroll
    for (int o = 16; o > 0; o >>= 1) m = fmaxf(m, __shfl_xor_sync(~0u, m, o));
    if ((threadIdx.x & 31) == 0) atomicMax(&g_emax_bits, __float_as_uint(m));
}
// z [B,D,T] -> token-major fp32
__global__ void k_tr(const float* __restrict__ z) {
    __shared__ float ts[32][33];
    int t0 = blockIdx.x * 32, d0 = blockIdx.y * 32, b = blockIdx.z;
    int tx = threadIdx.x & 31, ty = threadIdx.x >> 5;
    #pragma unroll
    for (int p = 0; p < 4; p++) {
        int dd = ty + p * 8;
        ts[dd][tx] = z[((size_t)b * D_ + d0 + dd) * T_ + t0 + tx];
    }
    __syncthreads();
    float* zt = (float*)g_zt4;
    #pragma unroll
    for (int p = 0; p < 4; p++) {
        int tt = ty + p * 8;
        size_t n = (size_t)b * T_ + t0 + tt;
        zt[n * D_ + d0 + tx] = ts[tx][tt];
    }
}
// pack e -> int8 (global scale), record max row sum|e|
__global__ void k_epack(const float* __restrict__ emb) {
    int wid = threadIdx.x >> 5, lane = threadIdx.x & 31;
    int k = blockIdx.x * 8 + wid;
    float emax = fmaxf(__uint_as_float(g_emax_bits), 1e-30f);
    float sc = 127.0f / emax;
    const float4* src = (const float4*)(emb + (size_t)k * D_);
    float4 a = __ldg(src + 2 * lane), b = __ldg(src + 2 * lane + 1);
    float v[8] = {a.x, a.y, a.z, a.w, b.x, b.y, b.z, b.w};
    float sa = 0.0f;
    int q[8];
    #pragma unroll
    for (int c = 0; c < 8; c++) { sa += fabsf(v[c]); q[c] = __float2int_rn(v[c] * sc); }
    int p0 = (q[0] & 255) | ((q[1] & 255) << 8) | ((q[2] & 255) << 16) | (q[3] << 24);
    int p1 = (q[4] & 255) | ((q[5] & 255) << 8) | ((q[6] & 255) << 16) | (q[7] << 24);
    ((int2*)(g_eq8 + (size_t)k * 64))[lane] = make_int2(p0, p1);
    #pragma unroll
    for (int o = 16; o > 0; o >>= 1) sa += __shfl_xor_sync(~0u, sa, o);
    if (lane == 0) atomicMax(&g_sae_bits, __float_as_uint(sa));
}
// pack z -> int8 per-token scale; per-token sound threshold
__global__ void k_zpack() {
    int wid = threadIdx.x >> 5, lane = threadIdx.x & 31;
    int n = blockIdx.x * 8 + wid;
    float emax = fmaxf(__uint_as_float(g_emax_bits), 1e-30f);
    float sae  = __uint_as_float(g_sae_bits);
    const float4* src = g_zt4 + (size_t)n * 64;
    float4 a = src[2 * lane], b = src[2 * lane + 1];
    float v[8] = {a.x, a.y, a.z, a.w, b.x, b.y, b.z, b.w};
    float rm = 0.0f, sz = 0.0f;
    #pragma unroll
    for (int c = 0; c < 8; c++) { float av = fabsf(v[c]); rm = fmaxf(rm, av); sz += av; }
    #pragma unroll
    for (int o = 16; o > 0; o >>= 1) {
        rm = fmaxf(rm, __shfl_xor_sync(~0u, rm, o));
        sz += __shfl_xor_sync(~0u, sz, o);
    }
    rm = fmaxf(rm, 1e-30f);
    float sc = 127.0f / rm;
    int q[8];
    #pragma unroll
    for (int c = 0; c < 8; c++) q[c] = __float2int_rn(v[c] * sc);
    int p0 = (q[0] & 255) | ((q[1] & 255) << 8) | ((q[2] & 255) << 16) | (q[3] << 24);
    int p1 = (q[4] & 255) | ((q[5] & 255) << 8) | ((q[6] & 255) << 16) | (q[7] << 24);
    ((int2*)(g_zq8 + (size_t)n * 64))[lane] = make_int2(p0, p1);
    if (lane == 0) {
        float hz = rm / 254.0f, he = emax / 254.0f;
        g_zrs[n] = (rm * emax) / 16129.0f;                       // zstep*estep
        g_thr[n] = 2.0f * (hz * sae + he * sz + 768.0f * hz * he) + 1.0e-4f;
    }
}

// ---------------------------------------------------------------------------
// screen: int8 dp4a GEMM + per-32-code block minima of (e2 - 2*dot)
// 128 tokens/CTA resident; loop 64 tiles of 128 codes; pitch-132 smem.
// ---------------------------------------------------------------------------
#define SPITCH 132
#define SCR_SMEM (2 * 64 * SPITCH * 4 + 512)   // zs + es + es2

__global__ __launch_bounds__(256, 2) void k_screen() {
    extern __shared__ __align__(16) int smi[];
    int* zs = smi;                      // [64][132]
    int* es = smi + 64 * SPITCH;        // [64][132]
    float* es2 = (float*)(smi + 2 * 64 * SPITCH);
    int tid = threadIdx.x, lane = tid & 31;
    int tm = tid >> 4, tn = tid & 15;
    int n0 = blockIdx.x * 128;

    // resident z tile (transpose [code-row][int-dim] -> [int-dim][row])
    const int4* zsrc = (const int4*)(g_zq8 + (size_t)n0 * 64);
    #pragma unroll
    for (int it = 0; it < 8; it++) {
        int idx4 = tid + it * 256;
        int r = idx4 >> 4, d4 = idx4 & 15;
        int4 v = zsrc[idx4];
        zs[(d4 * 4 + 0) * SPITCH + r] = v.x;
        zs[(d4 * 4 + 1) * SPITCH + r] = v.y;
        zs[(d4 * 4 + 2) * SPITCH + r] = v.z;
        zs[(d4 * 4 + 3) * SPITCH + r] = v.w;
    }
    float rs_lo[4], rs_hi[4];
    #pragma unroll
    for (int i = 0; i < 4; i++) {
        rs_lo[i] = g_zrs[n0 + tm * 4 + i];
        rs_hi[i] = g_zrs[n0 + 64 + tm * 4 + i];
    }

    for (int kt = 0; kt < 64; kt++) {
        __syncthreads();
        const int4* esrc = (const int4*)(g_eq8 + (size_t)kt * 128 * 64);
        #pragma unroll
        for (int it = 0; it < 8; it++) {
            int idx4 = tid + it * 256;
            int r = idx4 >> 4, d4 = idx4 & 15;
            int4 v = esrc[idx4];
            es[(d4 * 4 + 0) * SPITCH + r] = v.x;
            es[(d4 * 4 + 1) * SPITCH + r] = v.y;
            es[(d4 * 4 + 2) * SPITCH + r] = v.z;
            es[(d4 * 4 + 3) * SPITCH + r] = v.w;
        }
        if (tid < 128) es2[tid] = __ldg(g_e2 + kt * 128 + tid);
        __syncthreads();

        int acc[8][8];
        #pragma unroll
        for (int i = 0; i < 8; i++)
            #pragma unroll
            for (int j = 0; j < 8; j++) acc[i][j] = 0;

        #pragma unroll 4
        for (int di = 0; di < 64; di++) {
            int za[8], eb[8];
            *(int4*)&za[0] = *(const int4*)&zs[di * SPITCH + tm * 4];
            *(int4*)&za[4] = *(const int4*)&zs[di * SPITCH + 64 + tm * 4];
            *(int4*)&eb[0] = *(const int4*)&es[di * SPITCH + tn * 4];
            *(int4*)&eb[4] = *(const int4*)&es[di * SPITCH + 64 + tn * 4];
            #pragma unroll
            for (int i = 0; i < 8; i++)
                #pragma unroll
                for (int j = 0; j < 8; j++)
                    acc[i][j] = __dp4a(za[i], eb[j], acc[i][j]);
        }

        // epilogue: per-row minima over this tile's two code-halves
        #pragma unroll
        for (int i = 0; i < 8; i++) {
            float rs = (i < 4) ? rs_lo[i] : rs_hi[i - 4];
            float mlo = 3.4e38f, mhi = 3.4e38f;
            #pragma unroll
            for (int j = 0; j < 4; j++) {
                mlo = fminf(mlo, fmaf((float)acc[i][j]     * rs, -2.0f, es2[tn * 4 + j]));
                mhi = fminf(mhi, fmaf((float)acc[i][j + 4] * rs, -2.0f, es2[64 + tn * 4 + j]));
            }
            mlo = fminf(mlo, __shfl_xor_sync(~0u, mlo, 1));
            mlo = fminf(mlo, __shfl_xor_sync(~0u, mlo, 2));
            mlo = fminf(mlo, __shfl_xor_sync(~0u, mlo, 4));
            mhi = fminf(mhi, __shfl_xor_sync(~0u, mhi, 1));
            mhi = fminf(mhi, __shfl_xor_sync(~0u, mhi, 2));
            mhi = fminf(mhi, __shfl_xor_sync(~0u, mhi, 4));
            if ((lane & 7) == 0) {
                int jb = (lane >> 3) & 1;
                int tok = n0 + ((i < 4) ? (tm * 4 + i) : (64 + tm * 4 + (i - 4)));
                g_bmin[(size_t)(kt * 4 + jb) * N_ + tok]     = mlo;
                g_bmin[(size_t)(kt * 4 + 2 + jb) * N_ + tok] = mhi;
            }
        }
    }
}

// ---------------------------------------------------------------------------
// rescue: exact fp32 rescore of blocks within per-token sound margin
// ---------------------------------------------------------------------------
__global__ __launch_bounds__(128) void k_rescue(const float* __restrict__ emb) {
    __shared__ float zr[4][D_];
    int wid = threadIdx.x >> 5, lane = threadIdx.x & 31;
    int n = blockIdx.x * 4 + wid;

    const float4* zrow = (const float4*)(g_zt4 + (size_t)n * 64);
    #pragma unroll
    for (int q = 0; q < 2; q++) ((float4*)zr[wid])[lane + q * 32] = zrow[lane + q * 32];

    float bmv[8], mn = 3.4e38f;
    #pragma unroll
    for (int q = 0; q < 8; q++) {
        bmv[q] = g_bmin[(size_t)(q * 32 + lane) * N_ + n];
        mn = fminf(mn, bmv[q]);
    }
    #pragma unroll
    for (int o = 16; o > 0; o >>= 1) mn = fminf(mn, __shfl_xor_sync(~0u, mn, o));
    float thr = mn + g_thr[n];
    float z2 = g_z2[n];
    __syncwarp();

    float bd = 3.4e38f;
    int   bk = 0x7fffffff;
    for (int g = 0; g < 8; g++) {
        unsigned mask = __ballot_sync(~0u, bmv[g] <= thr);
        while (mask) {
            int bit = __ffs(mask) - 1;
            mask &= mask - 1;
            int k = (g * 32 + bit) * 32 + lane;
            const float4* e4 = (const float4*)(emb + (size_t)k * D_);
            const float4* z4 = (const float4*)zr[wid];
            float acc = 0.0f;
            #pragma unroll 16
            for (int f = 0; f < 64; f++) {
                float4 ev = __ldg(e4 + f);
                float4 zv = z4[f];
                acc = fmaf(zv.x, ev.x, acc); acc = fmaf(zv.y, ev.y, acc);
                acc = fmaf(zv.z, ev.z, acc); acc = fmaf(zv.w, ev.w, acc);
            }
            float dv = __fsub_rn(__fadd_rn(z2, g_e2[k]), __fmul_rn(2.0f, acc));
            if (dv < bd || (dv == bd && k < bk)) { bd = dv; bk = k; }
        }
    }
    #pragma unroll
    for (int o = 16; o > 0; o >>= 1) {
        float od = __shfl_xor_sync(~0u, bd, o);
        int   ok = __shfl_xor_sync(~0u, bk, o);
        if (od < bd || (od == bd && ok < bk)) { bd = od; bk = ok; }
    }
    if (lane == 0) g_idx[n] = bk;
}

// ---------------------------------------------------------------------------
// output: gather + straight-through rounding + loss partials (rel_err-0 version)
// ---------------------------------------------------------------------------
__global__ __launch_bounds__(256) void k_out(const float* __restrict__ emb,
                                             float* __restrict__ out,
                                             int write_zq, int write_idx, int idx_off) {
    __shared__ float s_sm[32][257];
    int tid = threadIdx.x, lane = tid & 31, w = tid >> 5;
    int n0 = blockIdx.x * 32;
    int b = n0 >> 12, t0 = n0 & 4095;
    const float* zt = (const float*)g_zt4;

    #pragma unroll
    for (int tt = 0; tt < 4; tt++) {
        int j = w * 4 + tt;
        int n = n0 + j;
        int idx = g_idx[n];
        const float* e  = emb + (size_t)idx * D_;
        const float* zp = zt + (size_t)n * D_;
        float lp = 0.0f;
        #pragma unroll
        for (int q = 0; q < 8; q++) {
            int d = lane + q * 32;
            float ev = __ldg(e + d);
            float zv = zp[d];
            float df = __fsub_rn(ev, zv);
            lp = fmaf(df, df, lp);
            if (write_zq) s_sm[j][d] = __fadd_rn(zv, df);
        }
        #pragma unroll
        for (int o = 16; o > 0; o >>= 1) lp += __shfl_xor_sync(~0u, lp, o);
        if (lane == 0) g_lpart[n] = lp;
    }
    if (write_idx && tid < 32) out[(size_t)idx_off + n0 + tid] = (float)g_idx[n0 + tid];
    if (!write_zq) return;
    __syncthreads();
    #pragma unroll
    for (int dc = 0; dc < 32; dc++) {
        int d = w + dc * 8;
        out[((size_t)b * D_ + d) * T_ + t0 + lane] = s_sm[lane][d];
    }
}
__global__ void k_loss(float* __restrict__ out, int loss_off) {
    __shared__ float sm[1024];
    int tid = threadIdx.x;
    float s = 0.0f;
    #pragma unroll 4
    for (int i = 0; i < 32; i++) s += g_lpart[tid * 32 + i];
    sm[tid] = s;
    __syncthreads();
    for (int w = 512; w > 0; w >>= 1) {
        if (tid < w) sm[tid] += sm[tid + w];
        __syncthreads();
    }
    if (tid == 0) out[loss_off] = 1.25f * (sm[0] / 8388608.0f);
}

extern "C" void kernel_launch(void* const* d_in, const int* in_sizes, int n_in,
                              void* d_out, int out_size) {
    const float* z   = (const float*)d_in[0];
    const float* emb = (const float*)d_in[1];
    if (n_in >= 2 && in_sizes[0] == K_ * D_ && in_sizes[1] == N_ * D_) {
        z = (const float*)d_in[1]; emb = (const float*)d_in[0];
    }
    float* out = (float*)d_out;

    cudaFuncSetAttribute(k_screen, cudaFuncAttributeMaxDynamicSharedMemorySize, SCR_SMEM);

    k_z2<<<N_ / 256, 256>>>(z);
    k_e2<<<K_ / 256, 256>>>(emb);
    k_emax<<<K_ * D_ / 1024, 256>>>(emb);
    k_tr<<<dim3(T_ / 32, D_ / 32, B_), 256>>>(z);
    k_epack<<<K_ / 8, 256>>>(emb);
    k_zpack<<<N_ / 8, 256>>>();
    k_screen<<<N_ / 128, 256, SCR_SMEM>>>();
    k_rescue<<<N_ / 4, 128>>>(emb);

    const int ZQ = N_ * D_;
    if (out_size == N_) {
        k_out<<<N_ / 32, 256>>>(emb, out, 0, 1, 0);
    } else {
        int write_zq = (out_size >= ZQ) ? 1 : 0;
        int write_loss = 0, write_idx = 0, idx_off = ZQ;
        if (out_size >= ZQ + 1 + N_) { write_loss = 1; write_idx = 1; idx_off = ZQ + 1; }
        else if (out_size == ZQ + N_) { write_idx = 1; idx_off = ZQ; }
        else if (out_size >= ZQ + 1) { write_loss = 1; }
        k_out<<<N_ / 32, 256>>>(emb, out, write_zq, write_idx, idx_off);
        if (write_loss) k_loss<<<1, 1024>>>(out, ZQ);
    }
}